// round 1
// baseline (speedup 1.0000x reference)
#include <cuda_runtime.h>
#include <cstdint>

// Problem constants
#define BATCH 32
#define DIM   256
#define HH    32
#define WW    32
#define HW    (HH*WW)          // 1024
#define NTOT  (BATCH*HW)       // 32768
#define KCODES 1024

#define ZQ_ELEMS   ((size_t)BATCH*DIM*HW)      // 8388608
#define CODES_OFF  ZQ_ELEMS
#define LOSS_OFF   (ZQ_ELEMS + (size_t)NTOT)   // 8421376

// GEMM tiling
#define TN 128
#define TK 128
#define TD 16
#define NBLOCKS (NTOT/TN)      // 256

__device__ float g_enorm[KCODES];
__device__ float g_partials[NBLOCKS];

// ---------------------------------------------------------------------------
// Kernel 1: ||e_k||^2 per codebook row. One warp per row.
// ---------------------------------------------------------------------------
__global__ void vq_enorm_kernel(const float* __restrict__ emb) {
    int gw   = (blockIdx.x * blockDim.x + threadIdx.x) >> 5;
    int lane = threadIdx.x & 31;
    if (gw < KCODES) {
        const float* row = emb + (size_t)gw * DIM;
        float s = 0.f;
        #pragma unroll
        for (int i = lane; i < DIM; i += 32) { float v = row[i]; s += v * v; }
        #pragma unroll
        for (int o = 16; o; o >>= 1) s += __shfl_xor_sync(0xFFFFFFFFu, s, o);
        if (lane == 0) g_enorm[gw] = s;
    }
}

// ---------------------------------------------------------------------------
// Kernel 2: main — per 128-row tile: fp32 GEMM vs all 1024 codes with running
// argmin, then gather z_q, write codes, accumulate loss partial.
// ---------------------------------------------------------------------------
__global__ __launch_bounds__(256, 2)
void vq_main_kernel(const float* __restrict__ z,
                    const float* __restrict__ emb,
                    float* __restrict__ out) {
    __shared__ float As[TD][TN];      // z tile, [d][n]
    __shared__ float Bs[TD][TK];      // emb tile, [d][k]
    __shared__ int   codes_s[TN];
    __shared__ float red_s[8];

    const int tid = threadIdx.x;
    const int tx  = tid & 15;         // k direction (8 cols each)
    const int ty  = tid >> 4;         // n direction (8 rows each)

    const int n0  = blockIdx.x * TN;
    const int b   = n0 >> 10;         // n0 / HW  (TN divides HW, so tile stays in one batch)
    const int hw0 = n0 & (HW - 1);
    // z_e[b][d][hw]: base for this tile; element (d, n_local) at +d*HW + n_local
    const float* zbase = z + (size_t)b * DIM * HW + hw0;

    float bestv[8];
    int   besti[8];
    #pragma unroll
    for (int i = 0; i < 8; i++) { bestv[i] = 3.4e38f; besti[i] = 0; }

    for (int kt = 0; kt < KCODES; kt += TK) {
        float acc[8][8];
        #pragma unroll
        for (int i = 0; i < 8; i++)
            #pragma unroll
            for (int j = 0; j < 8; j++) acc[i][j] = 0.f;

        for (int dt = 0; dt < DIM; dt += TD) {
            // Load A tile (TD x TN = 2048 floats) with float4, coalesced along n.
            #pragma unroll
            for (int i = 0; i < 2; i++) {
                int idx = tid + i * 256;          // 0..511 float4 slots
                int d   = idx >> 5;               // 32 float4 per row of 128
                int n4  = (idx & 31) << 2;
                float4 v = *reinterpret_cast<const float4*>(zbase + (size_t)(dt + d) * HW + n4);
                *reinterpret_cast<float4*>(&As[d][n4]) = v;
            }
            // Load B tile (TD x TK): emb is [K][D] row-major; read float4 along d,
            // transpose-store into Bs[d][k].
            #pragma unroll
            for (int i = 0; i < 2; i++) {
                int idx = tid + i * 256;          // 0..511
                int k   = idx >> 2;               // 4 float4 per k-row (TD=16)
                int d4  = (idx & 3) << 2;
                float4 v = *reinterpret_cast<const float4*>(emb + (size_t)(kt + k) * DIM + dt + d4);
                Bs[d4 + 0][k] = v.x;
                Bs[d4 + 1][k] = v.y;
                Bs[d4 + 2][k] = v.z;
                Bs[d4 + 3][k] = v.w;
            }
            __syncthreads();

            #pragma unroll
            for (int d = 0; d < TD; d++) {
                float4 a0 = *reinterpret_cast<const float4*>(&As[d][ty * 8]);
                float4 a1 = *reinterpret_cast<const float4*>(&As[d][ty * 8 + 4]);
                float4 b0 = *reinterpret_cast<const float4*>(&Bs[d][tx * 8]);
                float4 b1 = *reinterpret_cast<const float4*>(&Bs[d][tx * 8 + 4]);
                float a[8] = {a0.x, a0.y, a0.z, a0.w, a1.x, a1.y, a1.z, a1.w};
                float bb[8] = {b0.x, b0.y, b0.z, b0.w, b1.x, b1.y, b1.z, b1.w};
                #pragma unroll
                for (int i = 0; i < 8; i++)
                    #pragma unroll
                    for (int j = 0; j < 8; j++)
                        acc[i][j] += a[i] * bb[j];
            }
            __syncthreads();
        }

        // argmin update: score = ||e||^2 - 2*dot  (row-constant ||z||^2 dropped).
        // Iterate j ascending (k ascending) with strict < -> first-min tiebreak.
        #pragma unroll
        for (int j = 0; j < 8; j++) {
            int k = kt + tx * 8 + j;
            float en = g_enorm[k];
            #pragma unroll
            for (int i = 0; i < 8; i++) {
                float s = fmaf(-2.f, acc[i][j], en);
                if (s < bestv[i]) { bestv[i] = s; besti[i] = k; }
            }
        }
    }

    // Reduce argmin across the 16 tx-lanes sharing each row group.
    // Lanes ty*16+tx are 16 consecutive lanes -> xor shuffles stay in-group.
    #pragma unroll
    for (int i = 0; i < 8; i++) {
        float v = bestv[i];
        int  ix = besti[i];
        #pragma unroll
        for (int o = 8; o; o >>= 1) {
            float ov = __shfl_xor_sync(0xFFFFFFFFu, v, o);
            int   oi = __shfl_xor_sync(0xFFFFFFFFu, ix, o);
            if (ov < v || (ov == v && oi < ix)) { v = ov; ix = oi; }
        }
        if (tx == 0) codes_s[ty * 8 + i] = ix;
    }
    __syncthreads();

    // Codes output (as float), n-order matches reference (b,h,w) flatten.
    if (tid < TN) out[CODES_OFF + n0 + tid] = (float)codes_s[tid];

    // Gather z_q = emb[code], write back in (B,D,H,W) layout, accumulate loss.
    const int nl   = tid & 127;
    const int half = tid >> 7;            // 0/1 -> even/odd d
    const int code = codes_s[nl];
    const float* erow = emb + (size_t)code * DIM;
    float* out_zq = out + (size_t)b * DIM * HW + hw0;

    float lsum = 0.f;
    #pragma unroll 4
    for (int d = half; d < DIM; d += 2) {
        float v  = __ldg(erow + d);
        int  off = d * HW + nl;
        float zr = zbase[off];
        out_zq[off] = v;
        float diff = v - zr;
        lsum = fmaf(diff, diff, lsum);
    }

    // Block-reduce lsum, write deterministic per-block partial.
    #pragma unroll
    for (int o = 16; o; o >>= 1) lsum += __shfl_xor_sync(0xFFFFFFFFu, lsum, o);
    if ((tid & 31) == 0) red_s[tid >> 5] = lsum;
    __syncthreads();
    if (tid == 0) {
        float s = 0.f;
        #pragma unroll
        for (int w = 0; w < 8; w++) s += red_s[w];
        g_partials[blockIdx.x] = s;
    }
}

// ---------------------------------------------------------------------------
// Kernel 3: deterministic fixed-order loss finalize.
// ---------------------------------------------------------------------------
__global__ void vq_finalize_kernel(float* __restrict__ out) {
    if (threadIdx.x == 0 && blockIdx.x == 0) {
        float s = 0.f;
        for (int i = 0; i < NBLOCKS; i++) s += g_partials[i];
        // commit = mean + BETA*mean = 1.25 * sum / numel
        out[LOSS_OFF] = 1.25f * s / (float)ZQ_ELEMS;
    }
}

// ---------------------------------------------------------------------------
extern "C" void kernel_launch(void* const* d_in, const int* in_sizes, int n_in,
                              void* d_out, int out_size) {
    const float* z   = (const float*)d_in[0];
    const float* emb = (const float*)d_in[1];
    // Defensive: identify by element counts (z_e=8388608, embedding=262144).
    if (n_in >= 2 && in_sizes[0] == KCODES * DIM) {
        const float* t = z; z = emb; emb = t;
    }
    float* out = (float*)d_out;

    vq_enorm_kernel<<<(KCODES * 32 + 255) / 256, 256>>>(emb);
    vq_main_kernel<<<NBLOCKS, 256>>>(z, emb, out);
    vq_finalize_kernel<<<1, 32>>>(out);
}

// round 2
// speedup vs baseline: 1.0573x; 1.0573x over previous
#include <cuda_runtime.h>
#include <cstdint>

// Problem constants
#define BATCH 32
#define DIM   256
#define HH    32
#define WW    32
#define HW    (HH*WW)          // 1024
#define NTOT  (BATCH*HW)       // 32768
#define KCODES 1024

#define ZQ_ELEMS   ((size_t)BATCH*DIM*HW)      // 8388608
#define CODES_OFF  ZQ_ELEMS
#define LOSS_OFF   (ZQ_ELEMS + (size_t)NTOT)   // 8421376

// GEMM tiling
#define TN 128
#define TK 128
#define TD 16
#define NBLOCKS (NTOT/TN)      // 256

__device__ float g_enorm[KCODES];
__device__ float g_partials[NBLOCKS];

// ---------------------------------------------------------------------------
// Kernel 1: ||e_k||^2 per codebook row. One warp per row.
// ---------------------------------------------------------------------------
__global__ void vq_enorm_kernel(const float* __restrict__ emb) {
    int gw   = (blockIdx.x * blockDim.x + threadIdx.x) >> 5;
    int lane = threadIdx.x & 31;
    if (gw < KCODES) {
        const float* row = emb + (size_t)gw * DIM;
        float s = 0.f;
        #pragma unroll
        for (int i = lane; i < DIM; i += 32) { float v = row[i]; s += v * v; }
        #pragma unroll
        for (int o = 16; o; o >>= 1) s += __shfl_xor_sync(0xFFFFFFFFu, s, o);
        if (lane == 0) g_enorm[gw] = s;
    }
}

// ---------------------------------------------------------------------------
// Kernel 2: main — per 128-row tile: fp32 GEMM vs all 1024 codes with running
// argmin, then gather z_q, write codes, accumulate loss partial.
// ---------------------------------------------------------------------------
__global__ __launch_bounds__(256, 2)
void vq_main_kernel(const float* __restrict__ z,
                    const float* __restrict__ emb,
                    float* __restrict__ out) {
    __shared__ float As[TD][TN];      // z tile, [d][n]
    __shared__ float Bs[TD][TK];      // emb tile, [d][k]
    __shared__ int   codes_s[TN];
    __shared__ float red_s[8];

    const int tid = threadIdx.x;
    const int tx  = tid & 15;         // k direction (8 cols each)
    const int ty  = tid >> 4;         // n direction (8 rows each)

    const int n0  = blockIdx.x * TN;
    const int b   = n0 >> 10;         // n0 / HW  (TN divides HW, so tile stays in one batch)
    const int hw0 = n0 & (HW - 1);
    // z_e[b][d][hw]: base for this tile; element (d, n_local) at +d*HW + n_local
    const float* zbase = z + (size_t)b * DIM * HW + hw0;

    float bestv[8];
    int   besti[8];
    #pragma unroll
    for (int i = 0; i < 8; i++) { bestv[i] = 3.4e38f; besti[i] = 0; }

    for (int kt = 0; kt < KCODES; kt += TK) {
        float acc[8][8];
        #pragma unroll
        for (int i = 0; i < 8; i++)
            #pragma unroll
            for (int j = 0; j < 8; j++) acc[i][j] = 0.f;

        for (int dt = 0; dt < DIM; dt += TD) {
            // Load A tile (TD x TN = 2048 floats) with float4, coalesced along n.
            #pragma unroll
            for (int i = 0; i < 2; i++) {
                int idx = tid + i * 256;          // 0..511 float4 slots
                int d   = idx >> 5;               // 32 float4 per row of 128
                int n4  = (idx & 31) << 2;
                float4 v = *reinterpret_cast<const float4*>(zbase + (size_t)(dt + d) * HW + n4);
                *reinterpret_cast<float4*>(&As[d][n4]) = v;
            }
            // Load B tile (TD x TK): emb is [K][D] row-major; read float4 along d,
            // transpose-store into Bs[d][k].
            #pragma unroll
            for (int i = 0; i < 2; i++) {
                int idx = tid + i * 256;          // 0..511
                int k   = idx >> 2;               // 4 float4 per k-row (TD=16)
                int d4  = (idx & 3) << 2;
                float4 v = *reinterpret_cast<const float4*>(emb + (size_t)(kt + k) * DIM + dt + d4);
                Bs[d4 + 0][k] = v.x;
                Bs[d4 + 1][k] = v.y;
                Bs[d4 + 2][k] = v.z;
                Bs[d4 + 3][k] = v.w;
            }
            __syncthreads();

            #pragma unroll
            for (int d = 0; d < TD; d++) {
                float4 a0 = *reinterpret_cast<const float4*>(&As[d][ty * 8]);
                float4 a1 = *reinterpret_cast<const float4*>(&As[d][ty * 8 + 4]);
                float4 b0 = *reinterpret_cast<const float4*>(&Bs[d][tx * 8]);
                float4 b1 = *reinterpret_cast<const float4*>(&Bs[d][tx * 8 + 4]);
                float a[8] = {a0.x, a0.y, a0.z, a0.w, a1.x, a1.y, a1.z, a1.w};
                float bb[8] = {b0.x, b0.y, b0.z, b0.w, b1.x, b1.y, b1.z, b1.w};
                #pragma unroll
                for (int i = 0; i < 8; i++)
                    #pragma unroll
                    for (int j = 0; j < 8; j++)
                        acc[i][j] += a[i] * bb[j];
            }
            __syncthreads();
        }

        // argmin update: score = ||e||^2 - 2*dot  (row-constant ||z||^2 dropped).
        // Iterate j ascending (k ascending) with strict < -> first-min tiebreak.
        #pragma unroll
        for (int j = 0; j < 8; j++) {
            int k = kt + tx * 8 + j;
            float en = g_enorm[k];
            #pragma unroll
            for (int i = 0; i < 8; i++) {
                float s = fmaf(-2.f, acc[i][j], en);
                if (s < bestv[i]) { bestv[i] = s; besti[i] = k; }
            }
        }
    }

    // Reduce argmin across the 16 tx-lanes sharing each row group.
    // Lanes ty*16+tx are 16 consecutive lanes -> xor shuffles stay in-group.
    #pragma unroll
    for (int i = 0; i < 8; i++) {
        float v = bestv[i];
        int  ix = besti[i];
        #pragma unroll
        for (int o = 8; o; o >>= 1) {
            float ov = __shfl_xor_sync(0xFFFFFFFFu, v, o);
            int   oi = __shfl_xor_sync(0xFFFFFFFFu, ix, o);
            if (ov < v || (ov == v && oi < ix)) { v = ov; ix = oi; }
        }
        if (tx == 0) codes_s[ty * 8 + i] = ix;
    }
    __syncthreads();

    // Codes output (as float), n-order matches reference (b,h,w) flatten.
    if (tid < TN) out[CODES_OFF + n0 + tid] = (float)codes_s[tid];

    // Gather z_q = emb[code], write back in (B,D,H,W) layout, accumulate loss.
    const int nl   = tid & 127;
    const int half = tid >> 7;            // 0/1 -> even/odd d
    const int code = codes_s[nl];
    const float* erow = emb + (size_t)code * DIM;
    float* out_zq = out + (size_t)b * DIM * HW + hw0;

    float lsum = 0.f;
    #pragma unroll 4
    for (int d = half; d < DIM; d += 2) {
        float v  = __ldg(erow + d);
        int  off = d * HW + nl;
        float zr = zbase[off];
        out_zq[off] = v;
        float diff = v - zr;
        lsum = fmaf(diff, diff, lsum);
    }

    // Block-reduce lsum, write deterministic per-block partial.
    #pragma unroll
    for (int o = 16; o; o >>= 1) lsum += __shfl_xor_sync(0xFFFFFFFFu, lsum, o);
    if ((tid & 31) == 0) red_s[tid >> 5] = lsum;
    __syncthreads();
    if (tid == 0) {
        float s = 0.f;
        #pragma unroll
        for (int w = 0; w < 8; w++) s += red_s[w];
        g_partials[blockIdx.x] = s;
    }
}

// ---------------------------------------------------------------------------
// Kernel 3: deterministic fixed-order loss finalize.
// ---------------------------------------------------------------------------
__global__ void vq_finalize_kernel(float* __restrict__ out) {
    if (threadIdx.x == 0 && blockIdx.x == 0) {
        float s = 0.f;
        for (int i = 0; i < NBLOCKS; i++) s += g_partials[i];
        // commit = mean + BETA*mean = 1.25 * sum / numel
        out[LOSS_OFF] = 1.25f * s / (float)ZQ_ELEMS;
    }
}

// ---------------------------------------------------------------------------
extern "C" void kernel_launch(void* const* d_in, const int* in_sizes, int n_in,
                              void* d_out, int out_size) {
    const float* z   = (const float*)d_in[0];
    const float* emb = (const float*)d_in[1];
    // Defensive: identify by element counts (z_e=8388608, embedding=262144).
    if (n_in >= 2 && in_sizes[0] == KCODES * DIM) {
        const float* t = z; z = emb; emb = t;
    }
    float* out = (float*)d_out;

    vq_enorm_kernel<<<(KCODES * 32 + 255) / 256, 256>>>(emb);
    vq_main_kernel<<<NBLOCKS, 256>>>(z, emb, out);
    vq_finalize_kernel<<<1, 32>>>(out);
}

// round 4
// speedup vs baseline: 1.3874x; 1.3123x over previous
#include <cuda_runtime.h>
#include <cstdint>

#define DIM    256
#define HW     1024
#define NTOT   32768
#define KCODES 1024
#define MTILE  128
#define NBLOCKS (NTOT / MTILE)          // 256
#define ZQ_ELEMS  ((size_t)NTOT * DIM)
#define CODES_OFF ZQ_ELEMS
#define LOSS_OFF  (ZQ_ELEMS + (size_t)NTOT)

#define ASTR 136                        // A smem row stride (floats): conflict-free frags
#define BSTR 36                         // B smem row stride (floats): conflict-free frags

// dynamic smem layout (float offsets)
#define OFF_A   0
#define OFF_B   (256 * ASTR)                    // 34816
#define OFF_ES  (OFF_B + 2 * 128 * BSTR)        // 44032
#define OFF_RV  (OFF_ES + 1024)                 // 45056
#define OFF_RI  (OFF_RV + 256)                  // 45312
#define OFF_RED (OFF_RI + 256)                  // 45568
#define SMEM_FLOATS (OFF_RED + 8)               // 45576
#define SMEM_BYTES  (SMEM_FLOATS * 4)           // 182304

__device__ float g_enorm[KCODES];
__device__ float g_partials[NBLOCKS];

__device__ __forceinline__ uint32_t smem_u32(const void* p) {
    uint32_t a;
    asm("{ .reg .u64 t; cvta.to.shared.u64 t, %1; cvt.u32.u64 %0, t; }" : "=r"(a) : "l"(p));
    return a;
}
__device__ __forceinline__ void tf32_split(float x, uint32_t& h, uint32_t& l) {
    uint32_t hu;
    asm("cvt.rna.tf32.f32 %0, %1;" : "=r"(hu) : "f"(x));
    float hf = __uint_as_float(hu);
    uint32_t lu;
    asm("cvt.rna.tf32.f32 %0, %1;" : "=r"(lu) : "f"(x - hf));
    h = hu; l = lu;
}

#define MMA(c, a, b0, b1)                                                     \
    asm volatile("mma.sync.aligned.m16n8k8.row.col.f32.tf32.tf32.f32 "        \
        "{%0,%1,%2,%3}, {%4,%5,%6,%7}, {%8,%9}, {%0,%1,%2,%3};"               \
        : "+f"((c)[0]), "+f"((c)[1]), "+f"((c)[2]), "+f"((c)[3])              \
        : "r"((a)[0]), "r"((a)[1]), "r"((a)[2]), "r"((a)[3]),                 \
          "r"(b0), "r"(b1))

#define CP_ASYNC8(dst, src) \
    asm volatile("cp.async.ca.shared.global [%0], [%1], 8;" :: "r"(dst), "l"(src) : "memory")
#define CP_COMMIT() asm volatile("cp.async.commit_group;" ::: "memory")
#define CP_WAIT1()  asm volatile("cp.async.wait_group 1;" ::: "memory")
#define CP_WAIT0()  asm volatile("cp.async.wait_group 0;" ::: "memory")

// ---------------- prepass: ||e_k||^2 ----------------
__global__ void vq_enorm(const float* __restrict__ emb) {
    int gw = (blockIdx.x * blockDim.x + threadIdx.x) >> 5, lane = threadIdx.x & 31;
    if (gw < KCODES) {
        const float* row = emb + (size_t)gw * DIM;
        float s = 0.f;
        #pragma unroll
        for (int i = lane; i < DIM; i += 32) { float v = row[i]; s = fmaf(v, v, s); }
        #pragma unroll
        for (int o = 16; o; o >>= 1) s += __shfl_xor_sync(0xFFFFFFFFu, s, o);
        if (lane == 0) g_enorm[gw] = s;
    }
}

// issue cp.async loads for one B chunk: 128 codes x 32 dims, fp32, 8B copies
__device__ __forceinline__ void bload(const float* __restrict__ emb, int nc, int dc,
                                      float* dst, int tid) {
    const float* src = emb + (size_t)(nc * 128) * DIM + dc * 32;
    #pragma unroll
    for (int i = 0; i < 8; i++) {
        int idx = tid + i * 256;       // 0..2047 float2 slots
        int n = idx >> 4, j = idx & 15;
        uint32_t d = smem_u32(dst + n * BSTR + j * 2);
        CP_ASYNC8(d, src + (size_t)n * DIM + j * 2);
    }
}

// ---------------- main ----------------
__global__ __launch_bounds__(256, 1)
void vq_main(const float* __restrict__ z, const float* __restrict__ emb,
             float* __restrict__ out) {
    extern __shared__ __align__(16) float sm[];
    float* As  = sm + OFF_A;
    float* Bs  = sm + OFF_B;
    float* es  = sm + OFF_ES;
    float* rv  = sm + OFF_RV;
    int*   ri  = (int*)(sm + OFF_RI);
    float* red = sm + OFF_RED;

    const int tid = threadIdx.x, wid = tid >> 5, lane = tid & 31;
    const int wm = wid & 3, wn = wid >> 2;
    const int tig = lane & 3, grp = lane >> 2;

    const int n0 = blockIdx.x * MTILE;
    const int b = n0 >> 10, hw0 = n0 & (HW - 1);
    const float* zbase = z + (size_t)b * DIM * HW + hw0;

    // load A tile (256 d-rows x 128 n), fp32, coalesced float4
    #pragma unroll 8
    for (int i = 0; i < 32; i++) {
        int idx = tid + i * 256;
        int d = idx >> 5, c4 = idx & 31;
        float4 v = *reinterpret_cast<const float4*>(zbase + (size_t)d * HW + c4 * 4);
        *reinterpret_cast<float4*>(As + d * ASTR + c4 * 4) = v;
    }
    for (int i = tid; i < KCODES; i += 256) es[i] = g_enorm[i];
    __syncthreads();

    float bestv[4]; int besti[4];
    #pragma unroll
    for (int r = 0; r < 4; r++) { bestv[r] = 3.4e38f; besti[r] = 0; }

    const float* abase0 = As + wm * 32 + grp;       // + k*ASTR + mt*16 (+8)
    const float* bbase0 = Bs + (wn * 64 + grp) * BSTR + tig;

    for (int nc = 0; nc < 8; nc++) {
        float acc[2][8][4];
        #pragma unroll
        for (int mt = 0; mt < 2; mt++)
            #pragma unroll
            for (int nt = 0; nt < 8; nt++)
                #pragma unroll
                for (int q = 0; q < 4; q++) acc[mt][nt][q] = 0.f;

        bload(emb, nc, 0, Bs, tid);
        CP_COMMIT();

        #pragma unroll 1
        for (int dc = 0; dc < 8; dc++) {
            const int buf = dc & 1;
            if (dc < 7) {
                bload(emb, nc, dc + 1, Bs + (buf ^ 1) * 128 * BSTR, tid);
                CP_COMMIT();
                CP_WAIT1();
            } else {
                CP_WAIT0();
            }
            __syncthreads();

            const float* bb0 = bbase0 + buf * 128 * BSTR;
            #pragma unroll
            for (int kk = 0; kk < 4; kk++) {
                const int kb = dc * 32 + kk * 8;
                uint32_t ah[2][4], al[2][4];
                #pragma unroll
                for (int mt = 0; mt < 2; mt++) {
                    const float* ab = abase0 + (size_t)(kb + tig) * ASTR + mt * 16;
                    float f0 = ab[0], f1 = ab[8];
                    float f2 = ab[4 * ASTR], f3 = ab[4 * ASTR + 8];
                    tf32_split(f0, ah[mt][0], al[mt][0]);
                    tf32_split(f1, ah[mt][1], al[mt][1]);
                    tf32_split(f2, ah[mt][2], al[mt][2]);
                    tf32_split(f3, ah[mt][3], al[mt][3]);
                }
                #pragma unroll
                for (int nt = 0; nt < 8; nt++) {
                    const float* bp = bb0 + nt * 8 * BSTR + kk * 8;
                    float g0 = bp[0], g1 = bp[4];
                    uint32_t bh0, bl0, bh1, bl1;
                    tf32_split(g0, bh0, bl0);
                    tf32_split(g1, bh1, bl1);
                    #pragma unroll
                    for (int mt = 0; mt < 2; mt++) {
                        MMA(acc[mt][nt], ah[mt], bh0, bh1);
                        MMA(acc[mt][nt], ah[mt], bl0, bl1);
                        MMA(acc[mt][nt], al[mt], bh0, bh1);
                    }
                }
            }
            __syncthreads();
        }

        // fused argmin (ascending n, strict < => first-min tie-break)
        #pragma unroll
        for (int nt = 0; nt < 8; nt++) {
            const int n = nc * 128 + wn * 64 + nt * 8 + tig * 2;
            const float e0 = es[n], e1 = es[n + 1];
            #pragma unroll
            for (int mt = 0; mt < 2; mt++) {
                float s0 = fmaf(-2.f, acc[mt][nt][0], e0);
                float s1 = fmaf(-2.f, acc[mt][nt][1], e1);
                float s2 = fmaf(-2.f, acc[mt][nt][2], e0);
                float s3 = fmaf(-2.f, acc[mt][nt][3], e1);
                const int r0 = mt * 2, r1 = mt * 2 + 1;
                if (s0 < bestv[r0]) { bestv[r0] = s0; besti[r0] = n; }
                if (s1 < bestv[r0]) { bestv[r0] = s1; besti[r0] = n + 1; }
                if (s2 < bestv[r1]) { bestv[r1] = s2; besti[r1] = n; }
                if (s3 < bestv[r1]) { bestv[r1] = s3; besti[r1] = n + 1; }
            }
        }
    }

    // reduce across the 4 lanes (tig) that share each row
    #pragma unroll
    for (int r = 0; r < 4; r++) {
        float v = bestv[r]; int ix = besti[r];
        #pragma unroll
        for (int o = 1; o <= 2; o <<= 1) {
            float ov = __shfl_xor_sync(0xFFFFFFFFu, v, o);
            int   oi = __shfl_xor_sync(0xFFFFFFFFu, ix, o);
            if (ov < v || (ov == v && oi < ix)) { v = ov; ix = oi; }
        }
        if (tig == 0) {
            const int mt = r >> 1, rh = r & 1;
            const int row = wm * 32 + mt * 16 + rh * 8 + grp;
            rv[wn * 128 + row] = v;
            ri[wn * 128 + row] = ix;
        }
    }
    __syncthreads();

    // combine the two n-warp halves, write codes
    if (tid < 128) {
        float v0 = rv[tid], v1 = rv[128 + tid];
        int i0 = ri[tid], i1 = ri[128 + tid];
        int code = (v1 < v0 || (v1 == v0 && i1 < i0)) ? i1 : i0;
        ri[tid] = code;
        out[CODES_OFF + n0 + tid] = (float)code;
    }
    __syncthreads();

    // gather z_q + loss
    const int nl = tid & 127, half = tid >> 7;
    const int code = ri[nl];
    const float4* er = reinterpret_cast<const float4*>(emb + (size_t)code * DIM);
    float* zq = out + (size_t)b * DIM * HW + hw0 + nl;
    const float* zr = zbase + nl;
    float lsum = 0.f;
    #pragma unroll 4
    for (int d4 = half; d4 < 64; d4 += 2) {
        float4 e = __ldg(er + d4);
        const int o0 = (d4 * 4) * HW;
        float z0 = zr[o0], z1 = zr[o0 + HW], z2 = zr[o0 + 2 * HW], z3 = zr[o0 + 3 * HW];
        zq[o0] = e.x; zq[o0 + HW] = e.y; zq[o0 + 2 * HW] = e.z; zq[o0 + 3 * HW] = e.w;
        float d0 = e.x - z0, d1 = e.y - z1, d2 = e.z - z2, d3 = e.w - z3;
        lsum = fmaf(d0, d0, lsum); lsum = fmaf(d1, d1, lsum);
        lsum = fmaf(d2, d2, lsum); lsum = fmaf(d3, d3, lsum);
    }
    #pragma unroll
    for (int o = 16; o; o >>= 1) lsum += __shfl_xor_sync(0xFFFFFFFFu, lsum, o);
    if (lane == 0) red[wid] = lsum;
    __syncthreads();
    if (tid == 0) {
        float s = 0.f;
        #pragma unroll
        for (int w = 0; w < 8; w++) s += red[w];
        g_partials[blockIdx.x] = s;
    }
}

// ---------------- finalize ----------------
__global__ void vq_fin(float* __restrict__ out) {
    if (threadIdx.x == 0 && blockIdx.x == 0) {
        float s = 0.f;
        for (int i = 0; i < NBLOCKS; i++) s += g_partials[i];
        out[LOSS_OFF] = 1.25f * s / (float)ZQ_ELEMS;
    }
}

extern "C" void kernel_launch(void* const* d_in, const int* in_sizes, int n_in,
                              void* d_out, int out_size) {
    const float* z   = (const float*)d_in[0];
    const float* emb = (const float*)d_in[1];
    if (n_in >= 2 && in_sizes[0] == KCODES * DIM) { const float* t = z; z = emb; emb = t; }
    float* out = (float*)d_out;

    cudaFuncSetAttribute(vq_main, cudaFuncAttributeMaxDynamicSharedMemorySize, SMEM_BYTES);
    vq_enorm<<<(KCODES * 32 + 255) / 256, 256>>>(emb);
    vq_main<<<NBLOCKS, 256, SMEM_BYTES>>>(z, emb, out);
    vq_fin<<<1, 32>>>(out);
}

// round 5
// speedup vs baseline: 2.5995x; 1.8736x over previous
#include <cuda_runtime.h>
#include <cstdint>

#define DIM    256
#define HW     1024
#define NTOT   32768
#define KCODES 1024
#define MTILE  128
#define NBLOCKS (NTOT / MTILE)          // 256
#define ZQ_ELEMS  ((size_t)NTOT * DIM)
#define CODES_OFF ZQ_ELEMS
#define LOSS_OFF  (ZQ_ELEMS + (size_t)NTOT)

#define AKP   132                        // A row stride in half2 (128 + 4 pad)
#define BSTRH 20                         // B row stride in half2 (16 + 4 pad)

// dynamic smem layout in 4B words
#define OFF_AHI 0                        // 128 * 132 = 16896
#define OFF_ALO 16896
#define OFF_B   33792                    // 2 bufs x (hi 2560 + lo 2560) = 10240
#define BBUF_W  5120
#define OFF_ES  44032                    // 1024
#define OFF_RV  45056                    // 256
#define OFF_RI  45312                    // 256
#define OFF_RED 45568                    // 8
#define SMEM_WORDS 45576
#define SMEM_BYTES (SMEM_WORDS * 4)      // 182304

__device__ float g_enorm[KCODES];
__device__ float g_partials[NBLOCKS];

// pack two fp32 -> half2 {lo=x0, hi=x1}, plus residuals packed the same way
__device__ __forceinline__ void split2(float x0, float x1, uint32_t& h2, uint32_t& l2) {
    asm("cvt.rn.f16x2.f32 %0, %1, %2;" : "=r"(h2) : "f"(x1), "f"(x0));
    float f0, f1;
    asm("{ .reg .b16 l,h; mov.b32 {l,h}, %2; cvt.f32.f16 %0, l; cvt.f32.f16 %1, h; }"
        : "=f"(f0), "=f"(f1) : "r"(h2));
    asm("cvt.rn.f16x2.f32 %0, %1, %2;" : "=r"(l2) : "f"(x1 - f1), "f"(x0 - f0));
}

#define MMA16(c, a, b0, b1)                                                   \
    asm volatile("mma.sync.aligned.m16n8k16.row.col.f32.f16.f16.f32 "         \
        "{%0,%1,%2,%3}, {%4,%5,%6,%7}, {%8,%9}, {%0,%1,%2,%3};"               \
        : "+f"((c)[0]), "+f"((c)[1]), "+f"((c)[2]), "+f"((c)[3])              \
        : "r"((a)[0]), "r"((a)[1]), "r"((a)[2]), "r"((a)[3]),                 \
          "r"(b0), "r"(b1))

// ---------------- prepass: ||e_k||^2 ----------------
__global__ void vq_enorm(const float* __restrict__ emb) {
    int gw = (blockIdx.x * blockDim.x + threadIdx.x) >> 5, lane = threadIdx.x & 31;
    if (gw < KCODES) {
        const float* row = emb + (size_t)gw * DIM;
        float s = 0.f;
        #pragma unroll
        for (int i = lane; i < DIM; i += 32) { float v = row[i]; s = fmaf(v, v, s); }
        #pragma unroll
        for (int o = 16; o; o >>= 1) s += __shfl_xor_sync(0xFFFFFFFFu, s, o);
        if (lane == 0) g_enorm[gw] = s;
    }
}

// stage one B chunk (128 codes x 32 dims fp32) into registers
__device__ __forceinline__ void b_ldg(const float* __restrict__ emb, int c,
                                      float2* v, int tid) {
    const int nc = c >> 3, dc = c & 7;
    const float* src = emb + (size_t)(nc * 128) * DIM + dc * 32;
    #pragma unroll
    for (int i = 0; i < 8; i++) {
        int idx = tid + i * 256;
        v[i] = *reinterpret_cast<const float2*>(src + (size_t)(idx >> 4) * DIM + (idx & 15) * 2);
    }
}
// split staged chunk and store to smem hi/lo half2
__device__ __forceinline__ void b_sts(uint32_t* __restrict__ bhi,
                                      uint32_t* __restrict__ blo,
                                      const float2* v, int tid) {
    #pragma unroll
    for (int i = 0; i < 8; i++) {
        int idx = tid + i * 256;
        uint32_t h2, l2;
        split2(v[i].x, v[i].y, h2, l2);
        int a = (idx >> 4) * BSTRH + (idx & 15);
        bhi[a] = h2; blo[a] = l2;
    }
}

// ---------------- main ----------------
__global__ __launch_bounds__(256, 1)
void vq_main(const float* __restrict__ z, const float* __restrict__ emb,
             float* __restrict__ out) {
    extern __shared__ __align__(16) uint32_t sw[];
    uint32_t* sAhi = sw + OFF_AHI;
    uint32_t* sAlo = sw + OFF_ALO;
    float*    es   = reinterpret_cast<float*>(sw + OFF_ES);
    float*    rv   = reinterpret_cast<float*>(sw + OFF_RV);
    int*      ri   = reinterpret_cast<int*>(sw + OFF_RI);
    float*    red  = reinterpret_cast<float*>(sw + OFF_RED);

    const int tid = threadIdx.x, wid = tid >> 5, lane = tid & 31;
    const int wm = wid & 3, wn = wid >> 2;          // 4 m-warps x 2 n-warps
    const int tig = lane & 3, grp = lane >> 2;

    const int n0 = blockIdx.x * MTILE;
    const int b = n0 >> 10, hw0 = n0 & (HW - 1);
    const float* zbase = z + (size_t)b * DIM * HW + hw0;

    // ---- stage B chunk 0 early ----
    float2 stage[8];
    b_ldg(emb, 0, stage, tid);

    // ---- split A tile (256k x 128m) into Ahi/Alo half2 [m][kp] ----
    {
        const int m = tid & 127, kh = (tid >> 7) * 128;
        const float* zc = zbase + m;
        uint32_t* ah = sAhi + m * AKP + (kh >> 1);
        uint32_t* al = sAlo + m * AKP + (kh >> 1);
        #pragma unroll 4
        for (int j = 0; j < 64; j++) {
            const int k = kh + 2 * j;
            float x0 = zc[(size_t)k * HW], x1 = zc[(size_t)(k + 1) * HW];
            uint32_t h2, l2;
            split2(x0, x1, h2, l2);
            ah[j] = h2; al[j] = l2;
        }
    }
    for (int i = tid; i < KCODES; i += 256) es[i] = g_enorm[i];

    b_sts(sw + OFF_B, sw + OFF_B + 2560, stage, tid);
    __syncthreads();

    float bestv[4]; int besti[4];
    #pragma unroll
    for (int r = 0; r < 4; r++) { bestv[r] = 3.4e38f; besti[r] = 0; }

    float acc[2][8][4];

    #pragma unroll 1
    for (int c = 0; c < 64; c++) {
        const int nc = c >> 3, dc = c & 7, s = c & 1;
        if (dc == 0) {
            #pragma unroll
            for (int mt = 0; mt < 2; mt++)
                #pragma unroll
                for (int nt = 0; nt < 8; nt++)
                    #pragma unroll
                    for (int q = 0; q < 4; q++) acc[mt][nt][q] = 0.f;
        }
        if (c < 63) b_ldg(emb, c + 1, stage, tid);

        const uint32_t* bhi = sw + OFF_B + s * BBUF_W;
        const uint32_t* blo = bhi + 2560;

        #pragma unroll
        for (int kk = 0; kk < 2; kk++) {
            const int kpb = dc * 16 + kk * 8;
            uint32_t ah[2][4], al[2][4];
            #pragma unroll
            for (int mt = 0; mt < 2; mt++) {
                const uint32_t* Ah = sAhi + (wm * 32 + mt * 16 + grp) * AKP + kpb + tig;
                const uint32_t* Al = sAlo + (wm * 32 + mt * 16 + grp) * AKP + kpb + tig;
                ah[mt][0] = Ah[0]; ah[mt][1] = Ah[8 * AKP];
                ah[mt][2] = Ah[4]; ah[mt][3] = Ah[8 * AKP + 4];
                al[mt][0] = Al[0]; al[mt][1] = Al[8 * AKP];
                al[mt][2] = Al[4]; al[mt][3] = Al[8 * AKP + 4];
            }
            #pragma unroll
            for (int nt = 0; nt < 8; nt++) {
                const int nb = (wn * 64 + nt * 8 + grp) * BSTRH + kk * 8 + tig;
                const uint32_t bh0 = bhi[nb], bh1 = bhi[nb + 4];
                const uint32_t bl0 = blo[nb], bl1 = blo[nb + 4];
                #pragma unroll
                for (int mt = 0; mt < 2; mt++) {
                    MMA16(acc[mt][nt], ah[mt], bh0, bh1);
                    MMA16(acc[mt][nt], ah[mt], bl0, bl1);
                    MMA16(acc[mt][nt], al[mt], bh0, bh1);
                }
            }
        }

        if (c < 63) b_sts(sw + OFF_B + (s ^ 1) * BBUF_W,
                          sw + OFF_B + (s ^ 1) * BBUF_W + 2560, stage, tid);

        if (dc == 7) {
            // fused argmin (ascending n, strict < => first-min tie-break)
            #pragma unroll
            for (int nt = 0; nt < 8; nt++) {
                const int n = nc * 128 + wn * 64 + nt * 8 + tig * 2;
                const float e0 = es[n], e1 = es[n + 1];
                #pragma unroll
                for (int mt = 0; mt < 2; mt++) {
                    float s0 = fmaf(-2.f, acc[mt][nt][0], e0);
                    float s1 = fmaf(-2.f, acc[mt][nt][1], e1);
                    float s2 = fmaf(-2.f, acc[mt][nt][2], e0);
                    float s3 = fmaf(-2.f, acc[mt][nt][3], e1);
                    const int r0 = mt * 2, r1 = mt * 2 + 1;
                    if (s0 < bestv[r0]) { bestv[r0] = s0; besti[r0] = n; }
                    if (s1 < bestv[r0]) { bestv[r0] = s1; besti[r0] = n + 1; }
                    if (s2 < bestv[r1]) { bestv[r1] = s2; besti[r1] = n; }
                    if (s3 < bestv[r1]) { bestv[r1] = s3; besti[r1] = n + 1; }
                }
            }
        }
        __syncthreads();
    }

    // reduce across the 4 tig-lanes sharing each row
    #pragma unroll
    for (int r = 0; r < 4; r++) {
        float v = bestv[r]; int ix = besti[r];
        #pragma unroll
        for (int o = 1; o <= 2; o <<= 1) {
            float ov = __shfl_xor_sync(0xFFFFFFFFu, v, o);
            int   oi = __shfl_xor_sync(0xFFFFFFFFu, ix, o);
            if (ov < v || (ov == v && oi < ix)) { v = ov; ix = oi; }
        }
        if (tig == 0) {
            const int mt = r >> 1, rh = r & 1;
            const int row = wm * 32 + mt * 16 + rh * 8 + grp;
            rv[wn * 128 + row] = v;
            ri[wn * 128 + row] = ix;
        }
    }
    __syncthreads();

    // combine the two n-warp halves, write codes
    if (tid < 128) {
        float v0 = rv[tid], v1 = rv[128 + tid];
        int i0 = ri[tid], i1 = ri[128 + tid];
        int code = (v1 < v0 || (v1 == v0 && i1 < i0)) ? i1 : i0;
        ri[tid] = code;
        out[CODES_OFF + n0 + tid] = (float)code;
    }
    __syncthreads();

    // gather z_q + loss
    const int nl = tid & 127, half = tid >> 7;
    const int code = ri[nl];
    const float4* er = reinterpret_cast<const float4*>(emb + (size_t)code * DIM);
    float* zq = out + (size_t)b * DIM * HW + hw0 + nl;
    const float* zr = zbase + nl;
    float lsum = 0.f;
    #pragma unroll 4
    for (int d4 = half; d4 < 64; d4 += 2) {
        float4 e = __ldg(er + d4);
        const int o0 = (d4 * 4) * HW;
        float z0 = zr[o0], z1 = zr[o0 + HW], z2 = zr[o0 + 2 * HW], z3 = zr[o0 + 3 * HW];
        zq[o0] = e.x; zq[o0 + HW] = e.y; zq[o0 + 2 * HW] = e.z; zq[o0 + 3 * HW] = e.w;
        float d0 = e.x - z0, d1 = e.y - z1, d2 = e.z - z2, d3 = e.w - z3;
        lsum = fmaf(d0, d0, lsum); lsum = fmaf(d1, d1, lsum);
        lsum = fmaf(d2, d2, lsum); lsum = fmaf(d3, d3, lsum);
    }
    #pragma unroll
    for (int o = 16; o; o >>= 1) lsum += __shfl_xor_sync(0xFFFFFFFFu, lsum, o);
    if (lane == 0) red[wid] = lsum;
    __syncthreads();
    if (tid == 0) {
        float s = 0.f;
        #pragma unroll
        for (int w = 0; w < 8; w++) s += red[w];
        g_partials[blockIdx.x] = s;
    }
}

// ---------------- finalize ----------------
__global__ void vq_fin(float* __restrict__ out) {
    if (threadIdx.x == 0 && blockIdx.x == 0) {
        float s = 0.f;
        for (int i = 0; i < NBLOCKS; i++) s += g_partials[i];
        out[LOSS_OFF] = 1.25f * s / (float)ZQ_ELEMS;
    }
}

extern "C" void kernel_launch(void* const* d_in, const int* in_sizes, int n_in,
                              void* d_out, int out_size) {
    const float* z   = (const float*)d_in[0];
    const float* emb = (const float*)d_in[1];
    if (n_in >= 2 && in_sizes[0] == KCODES * DIM) { const float* t = z; z = emb; emb = t; }
    float* out = (float*)d_out;

    cudaFuncSetAttribute(vq_main, cudaFuncAttributeMaxDynamicSharedMemorySize, SMEM_BYTES);
    vq_enorm<<<(KCODES * 32 + 255) / 256, 256>>>(emb);
    vq_main<<<NBLOCKS, 256, SMEM_BYTES>>>(z, emb, out);
    vq_fin<<<1, 32>>>(out);
}